// round 3
// baseline (speedup 1.0000x reference)
#include <cuda_runtime.h>

// KalmanNetNN: sequential 100-step Kalman/GRU scan as one persistent kernel.
// fp32 throughout. Grid = numSMs CTAs x 1024 threads, software grid barriers.

#define M10   10
#define NTT   100
#define H1D   1600
#define H2D   400
#define HID   2000
#define G3D   6000
#define DIN   30

// ---------------- device scratch (static; no allocations allowed) ----------
__device__ float g_gh0p[G3D * 8];   // partial sums, 8 column-chunks per row
__device__ float g_gh1p[G3D * 8];
__device__ float g_gi0p[G3D * 8];
__device__ float g_gi1p[G3D * 8];
__device__ float g_gp[H2D * 8];
__device__ float g_a[H1D];
__device__ float g_post[M10], g_prev_post[M10], g_prev_prior[M10], g_yprev[M10];
__device__ float g_h1i[HID], g_h2i[HID];
__device__ unsigned g_bar;
__device__ unsigned g_epoch;

// ---------------- small math helpers ---------------------------------------
__device__ __forceinline__ float sigmoidf_(float x) {
    return 1.0f / (1.0f + expf(-x));
}
__device__ __forceinline__ float tanhf_(float x) {
    x = fminf(fmaxf(x, -15.0f), 15.0f);
    float e = expf(2.0f * x);
    return (e - 1.0f) / (e + 1.0f);
}

// warp-cooperative partial dot: columns [start, start+len) of row w against
// shared vector v. start%4==0, len%4==0, (start*4)%16==0 guaranteed by caller.
__device__ __forceinline__ float wdot(const float* __restrict__ w,
                                      const float* __restrict__ v,
                                      int start, int len, int lane) {
    float s = 0.0f;
    int end = start + len;
    for (int c = start + lane * 4; c < end; c += 128) {
        float4 a = *reinterpret_cast<const float4*>(w + c);
        float4 b = *reinterpret_cast<const float4*>(v + c);
        s = fmaf(a.x, b.x, s);
        s = fmaf(a.y, b.y, s);
        s = fmaf(a.z, b.z, s);
        s = fmaf(a.w, b.w, s);
    }
#pragma unroll
    for (int o = 16; o; o >>= 1) s += __shfl_xor_sync(0xffffffffu, s, o);
    return s;
}

__device__ __forceinline__ float warp_sum(float x) {
#pragma unroll
    for (int o = 16; o; o >>= 1) x += __shfl_xor_sync(0xffffffffu, x, o);
    return x;
}

// grid barrier: arrive + poll monotonic counter (reset by init kernel)
__device__ __forceinline__ void gsync(unsigned target) {
    __syncthreads();
    if (threadIdx.x == 0) {
        __threadfence();
        atomicAdd(&g_bar, 1u);
        while (*(volatile unsigned*)&g_bar < target) { }
        __threadfence();
    }
    __syncthreads();
}

// chunk geometry: K=2000 -> 7x256 + 208 ; K=1600 -> 8x200
__device__ __forceinline__ void chunk2000(int c, int& start, int& len) {
    start = c * 256;
    len = (c == 7) ? 208 : 256;
}

// ---------------- init kernel (runs each replay, resets all state) ---------
__global__ void knet_init(const float* __restrict__ m1x0,
                          const float* __restrict__ F,
                          const float* __restrict__ Hm,
                          const float* __restrict__ h0) {
    int t = threadIdx.x;
    __shared__ float fm[M10];
    if (t == 0) { g_bar = 0u; g_epoch = 0u; }
    if (t < M10) {
        float s = 0.0f;
        for (int j = 0; j < M10; j++) s = fmaf(F[t * M10 + j], m1x0[j], s);
        fm[t] = s;
        g_post[t] = m1x0[t];
        g_prev_post[t] = 0.0f;
        g_prev_prior[t] = m1x0[t];
    }
    __syncthreads();
    if (t < M10) {
        float s = 0.0f;
        for (int j = 0; j < M10; j++) s = fmaf(Hm[t * M10 + j], fm[j], s);
        g_yprev[t] = s;
    }
    for (int i = t; i < HID; i += blockDim.x) {
        g_h1i[i] = h0[i];
        g_h2i[i] = h0[HID + i];
    }
}

// ---------------- epilogue of step te (one warp: CTA0/warp0) ---------------
__device__ __forceinline__ void epilogue(int te, int lane,
                                         const float* __restrict__ y,
                                         const float* __restrict__ F,
                                         const float* __restrict__ Hm,
                                         const float* __restrict__ W3,
                                         const float* __restrict__ b3,
                                         const float* __restrict__ b2,
                                         float* __restrict__ out,
                                         float* s_scr) {
    float* s_g  = s_scr;        // 400
    float* s_kg = s_scr + 400;  // 100
    float* s_pr = s_scr + 512;  // 10
    float* s_dy = s_scr + 528;  // 10

    // g = relu(sum of partials + b2)
    for (int i = lane; i < H2D; i += 32) {
        float s = b2[i];
#pragma unroll
        for (int k = 0; k < 8; k++) s += g_gp[i * 8 + k];
        s_g[i] = fmaxf(s, 0.0f);
    }
    __syncwarp();
    // KG vec = W3 @ g + b3 (100 rows of 400)
    for (int r = lane; r < 100; r += 32) {
        const float* w = W3 + r * H2D;
        float s = b3[r];
        for (int j = 0; j < H2D; j += 4) {
            float4 a = *reinterpret_cast<const float4*>(w + j);
            s = fmaf(a.x, s_g[j],     s);
            s = fmaf(a.y, s_g[j + 1], s);
            s = fmaf(a.z, s_g[j + 2], s);
            s = fmaf(a.w, s_g[j + 3], s);
        }
        s_kg[r] = s;
    }
    __syncwarp();
    // prior = F @ post
    if (lane < M10) {
        float s = 0.0f;
        for (int j = 0; j < M10; j++) s = fmaf(F[lane * M10 + j], g_post[j], s);
        s_pr[lane] = s;
    }
    __syncwarp();
    // dy = yt - Hm @ prior
    if (lane < M10) {
        float m1y = 0.0f;
        for (int j = 0; j < M10; j++) m1y = fmaf(Hm[lane * M10 + j], s_pr[j], m1y);
        s_dy[lane] = y[lane * NTT + te] - m1y;
    }
    __syncwarp();
    // new_post = prior + KG @ dy ; rotate state ; write output column te
    if (lane < M10) {
        float np = s_pr[lane];
        for (int j = 0; j < M10; j++) np = fmaf(s_kg[lane * M10 + j], s_dy[j], np);
        g_prev_post[lane]  = g_post[lane];
        g_prev_prior[lane] = s_pr[lane];
        g_yprev[lane]      = y[lane * NTT + te];
        out[lane * NTT + te] = np;
        g_post[lane] = np;
    }
    __syncwarp();
}

// ---------------- main persistent kernel -----------------------------------
__global__ void __launch_bounds__(1024, 1)
knet_main(const float* __restrict__ y,
          const float* __restrict__ W1,  const float* __restrict__ b1,
          const float* __restrict__ Wi0, const float* __restrict__ Wh0,
          const float* __restrict__ bi0, const float* __restrict__ bh0,
          const float* __restrict__ Wi1, const float* __restrict__ Wh1,
          const float* __restrict__ bi1, const float* __restrict__ bh1,
          const float* __restrict__ W2,  const float* __restrict__ b2,
          const float* __restrict__ W3,  const float* __restrict__ b3,
          const float* __restrict__ F,   const float* __restrict__ Hm,
          float* __restrict__ out) {
    __shared__ __align__(16) float s_h1[HID];
    __shared__ __align__(16) float s_h2[HID];
    __shared__ __align__(16) float s_a[H1D];   // doubles as epilogue scratch
    __shared__ float s_kin[DIN];

    const int tid  = threadIdx.x;
    const int lane = tid & 31;
    const int wid  = tid >> 5;
    const unsigned gw = blockIdx.x * 32u + (unsigned)wid;
    const unsigned NW = gridDim.x * 32u;

    // stage initial GRU states into persistent smem
    for (int i = tid; i < HID; i += 1024) {
        s_h1[i] = g_h1i[i];
        s_h2[i] = g_h2i[i];
    }
    __syncthreads();

    unsigned tgt = 0;

    for (int t = 0; t < NTT; ++t) {
        // ---- Phase 1a: previous-step epilogue (CTA0.warp0) overlapped with
        //      gh0 = Wh0@h1, gh1 = Wh1@h2 (96 MB stream, 96000 chunk units)
        if (blockIdx.x == 0 && wid == 0 && t > 0) {
            epilogue(t - 1, lane, y, F, Hm, W3, b3, b2, out, s_a);
            if (lane == 0) {
                __threadfence();
                *(volatile unsigned*)&g_epoch = (unsigned)t;
            }
            __syncwarp();
        }
        for (unsigned u = gw; u < 96000u; u += NW) {
            unsigned v    = (u < 48000u) ? u : (u - 48000u);
            int      row  = (int)(v >> 3);
            int      cidx = (int)(v & 7u);
            int start, len;
            chunk2000(cidx, start, len);
            if (u < 48000u) {
                float d = wdot(Wh0 + (size_t)row * HID, s_h1, start, len, lane);
                if (lane == 0) g_gh0p[v] = d;
            } else {
                float d = wdot(Wh1 + (size_t)row * HID, s_h2, start, len, lane);
                if (lane == 0) g_gh1p[v] = d;
            }
        }
        __syncthreads();

        // ---- Phase 1b: wait for state update, compute normalized features
        if (wid == 0) {
            while (*(volatile unsigned*)&g_epoch < (unsigned)t) { }
            __threadfence();
            float yt = 0.0f, p = 0.0f, pp = 0.0f, ppr = 0.0f, yp = 0.0f;
            if (lane < M10) {
                yt  = y[lane * NTT + t];
                p   = g_post[lane];
                pp  = g_prev_post[lane];
                ppr = g_prev_prior[lane];
                yp  = g_yprev[lane];
            }
            float d1 = yt - yp;
            float d3 = p - pp;
            float d4 = p - ppr;
            float n1 = fmaxf(sqrtf(warp_sum(d1 * d1)), 1e-12f);
            float n3 = fmaxf(sqrtf(warp_sum(d3 * d3)), 1e-12f);
            float n4 = fmaxf(sqrtf(warp_sum(d4 * d4)), 1e-12f);
            if (lane < M10) {
                s_kin[lane]      = d1 / n1;
                s_kin[10 + lane] = d3 / n3;
                s_kin[20 + lane] = d4 / n4;
            }
        }
        __syncthreads();

        // ---- Phase 1c: a = relu(W1 @ kin + b1), 1600 row units
        for (unsigned r = gw; r < (unsigned)H1D; r += NW) {
            float s = (lane < DIN) ? W1[r * DIN + lane] * s_kin[lane] : 0.0f;
            s = warp_sum(s);
            if (lane == 0) g_a[r] = fmaxf(s + b1[r], 0.0f);
        }
        tgt += gridDim.x; gsync(tgt);

        // ---- Phase 2: gi0 = Wi0 @ a (48000 chunk units of 200 cols)
        for (int i = tid; i < H1D; i += 1024) s_a[i] = g_a[i];
        __syncthreads();
        for (unsigned u = gw; u < 48000u; u += NW) {
            int row  = (int)(u >> 3);
            int cidx = (int)(u & 7u);
            float d = wdot(Wi0 + (size_t)row * H1D, s_a, cidx * 200, 200, lane);
            if (lane == 0) g_gi0p[u] = d;
        }
        tgt += gridDim.x; gsync(tgt);

        // ---- Phase 3: h1n combine (per-CTA, into s_h1) then gi1 = Wi1 @ h1n
        for (int j = tid; j < HID; j += 1024) {
            float ir = bi0[j], iz = bi0[j + HID], inn = bi0[j + 2 * HID];
            float hr = bh0[j], hz = bh0[j + HID], hn  = bh0[j + 2 * HID];
#pragma unroll
            for (int k = 0; k < 8; k++) {
                ir  += g_gi0p[(size_t)j * 8 + k];
                iz  += g_gi0p[(size_t)(j + HID) * 8 + k];
                inn += g_gi0p[(size_t)(j + 2 * HID) * 8 + k];
                hr  += g_gh0p[(size_t)j * 8 + k];
                hz  += g_gh0p[(size_t)(j + HID) * 8 + k];
                hn  += g_gh0p[(size_t)(j + 2 * HID) * 8 + k];
            }
            float r  = sigmoidf_(ir + hr);
            float z  = sigmoidf_(iz + hz);
            float nn = tanhf_(inn + r * hn);
            float h  = s_h1[j];
            s_h1[j] = (1.0f - z) * nn + z * h;
        }
        __syncthreads();
        for (unsigned u = gw; u < 48000u; u += NW) {
            int row  = (int)(u >> 3);
            int cidx = (int)(u & 7u);
            int start, len;
            chunk2000(cidx, start, len);
            float d = wdot(Wi1 + (size_t)row * HID, s_h1, start, len, lane);
            if (lane == 0) g_gi1p[u] = d;
        }
        tgt += gridDim.x; gsync(tgt);

        // ---- Phase 4: h2n combine (into s_h2) then g partials = W2 @ h2n
        for (int j = tid; j < HID; j += 1024) {
            float ir = bi1[j], iz = bi1[j + HID], inn = bi1[j + 2 * HID];
            float hr = bh1[j], hz = bh1[j + HID], hn  = bh1[j + 2 * HID];
#pragma unroll
            for (int k = 0; k < 8; k++) {
                ir  += g_gi1p[(size_t)j * 8 + k];
                iz  += g_gi1p[(size_t)(j + HID) * 8 + k];
                inn += g_gi1p[(size_t)(j + 2 * HID) * 8 + k];
                hr  += g_gh1p[(size_t)j * 8 + k];
                hz  += g_gh1p[(size_t)(j + HID) * 8 + k];
                hn  += g_gh1p[(size_t)(j + 2 * HID) * 8 + k];
            }
            float r  = sigmoidf_(ir + hr);
            float z  = sigmoidf_(iz + hz);
            float nn = tanhf_(inn + r * hn);
            float h  = s_h2[j];
            s_h2[j] = (1.0f - z) * nn + z * h;
        }
        __syncthreads();
        for (unsigned u = gw; u < 3200u; u += NW) {
            int row  = (int)(u >> 3);
            int cidx = (int)(u & 7u);
            int start, len;
            chunk2000(cidx, start, len);
            float d = wdot(W2 + (size_t)row * HID, s_h2, start, len, lane);
            if (lane == 0) g_gp[u] = d;
        }
        tgt += gridDim.x; gsync(tgt);
    }

    // final epilogue for step T-1
    if (blockIdx.x == 0 && wid == 0) {
        epilogue(NTT - 1, lane, y, F, Hm, W3, b3, b2, out, s_a);
    }
}

// ---------------- launcher --------------------------------------------------
extern "C" void kernel_launch(void* const* d_in, const int* in_sizes, int n_in,
                              void* d_out, int out_size) {
    (void)in_sizes; (void)n_in; (void)out_size;
    const float* y    = (const float*)d_in[0];
    const float* m1x0 = (const float*)d_in[1];
    const float* F    = (const float*)d_in[2];
    const float* Hm   = (const float*)d_in[3];
    const float* h0   = (const float*)d_in[4];
    const float* W1   = (const float*)d_in[5];
    const float* b1   = (const float*)d_in[6];
    const float* Wi0  = (const float*)d_in[7];
    const float* Wh0  = (const float*)d_in[8];
    const float* bi0  = (const float*)d_in[9];
    const float* bh0  = (const float*)d_in[10];
    const float* Wi1  = (const float*)d_in[11];
    const float* Wh1  = (const float*)d_in[12];
    const float* bi1  = (const float*)d_in[13];
    const float* bh1  = (const float*)d_in[14];
    const float* W2   = (const float*)d_in[15];
    const float* b2   = (const float*)d_in[16];
    const float* W3   = (const float*)d_in[17];
    const float* b3   = (const float*)d_in[18];
    float* out = (float*)d_out;

    int dev = 0;
    cudaGetDevice(&dev);
    int nsm = 148;
    cudaDeviceGetAttribute(&nsm, cudaDevAttrMultiProcessorCount, dev);

    knet_init<<<1, 128>>>(m1x0, F, Hm, h0);
    knet_main<<<nsm, 1024>>>(y, W1, b1, Wi0, Wh0, bi0, bh0,
                             Wi1, Wh1, bi1, bh1, W2, b2, W3, b3,
                             F, Hm, out);
}

// round 4
// speedup vs baseline: 1.2622x; 1.2622x over previous
#include <cuda_runtime.h>
#include <cuda_fp16.h>

// KalmanNetNN: sequential 100-step Kalman/GRU scan, persistent kernel.
// Round 3: big weights converted once/launch to fp16 in padded __device__
// arrays (96.8 MB -> L2 resident); streaming restructured for MLP>=2.

#define M10   10
#define NTT   100
#define H1D   1600
#define H2D   400
#define HID   2000
#define G3D   6000
#define DIN   30

#define SW    2048          // padded stride for K=2000 matrices (8 chunks x 256)
#define SW0   1792          // padded stride for K=1600 matrix  (7 chunks x 256)
#define NCH   8
#define NCH0  7

// ---------------- device scratch (static; no allocations allowed) ----------
__device__ __half Wh0h[G3D * SW];
__device__ __half Wh1h[G3D * SW];
__device__ __half Wi1h[G3D * SW];
__device__ __half Wi0h[G3D * SW0];
__device__ __half W2h [H2D * SW];

__device__ float g_gh0p[G3D * NCH];
__device__ float g_gh1p[G3D * NCH];
__device__ float g_gi0p[G3D * NCH0];
__device__ float g_gi1p[G3D * NCH];
__device__ float g_gp  [H2D * NCH];
__device__ float g_a[H1D];
__device__ float g_post[M10], g_prev_post[M10], g_prev_prior[M10], g_yprev[M10];
__device__ float g_h1i[HID], g_h2i[HID];
__device__ unsigned g_bar;
__device__ unsigned g_epoch;

// ---------------- small math helpers ---------------------------------------
__device__ __forceinline__ float sigmoidf_(float x) {
    return 1.0f / (1.0f + expf(-x));
}
__device__ __forceinline__ float tanhf_(float x) {
    x = fminf(fmaxf(x, -15.0f), 15.0f);
    float e = expf(2.0f * x);
    return (e - 1.0f) / (e + 1.0f);
}
__device__ __forceinline__ float warp_sum(float x) {
#pragma unroll
    for (int o = 16; o; o >>= 1) x += __shfl_xor_sync(0xffffffffu, x, o);
    return x;
}

// dot of one 256-half chunk (lane loads uint4 = 8 halves) with fp32 smem vec
__device__ __forceinline__ float chunk_dot(const __half* __restrict__ wrow,
                                           const float* __restrict__ v,
                                           int chunk, int lane) {
    int c0 = chunk * 256 + lane * 8;
    uint4 wv = *reinterpret_cast<const uint4*>(wrow + c0);
    const __half2* hp = reinterpret_cast<const __half2*>(&wv);
    float s = 0.0f;
#pragma unroll
    for (int j = 0; j < 4; j++) {
        float2 f = __half22float2(hp[j]);
        s = fmaf(f.x, v[c0 + 2 * j],     s);
        s = fmaf(f.y, v[c0 + 2 * j + 1], s);
    }
    return s;
}

// grid barrier: arrive + poll monotonic counter (reset by init kernel)
__device__ __forceinline__ void gsync(unsigned target) {
    __syncthreads();
    if (threadIdx.x == 0) {
        __threadfence();
        atomicAdd(&g_bar, 1u);
        while (*(volatile unsigned*)&g_bar < target) { }
        __threadfence();
    }
    __syncthreads();
}

// ---------------- fp32 -> fp16 conversion (runs each launch) ---------------
__global__ void knet_cvt(const float* __restrict__ Wi0,
                         const float* __restrict__ Wh0,
                         const float* __restrict__ Wi1,
                         const float* __restrict__ Wh1,
                         const float* __restrict__ W2) {
    const int which = blockIdx.y;
    const unsigned stride = gridDim.x * blockDim.x;
    const unsigned t0 = blockIdx.x * blockDim.x + threadIdx.x;
    if (which < 3) {
        const float* src = (which == 0) ? Wh0 : (which == 1) ? Wh1 : Wi1;
        __half* dst = (which == 0) ? Wh0h : (which == 1) ? Wh1h : Wi1h;
        const unsigned n = G3D * SW;
        for (unsigned i = t0; i < n; i += stride) {
            unsigned col = i & (SW - 1);
            unsigned row = i >> 11;
            float v = (col < HID) ? src[row * HID + col] : 0.0f;
            dst[i] = __float2half_rn(v);
        }
    } else if (which == 3) {
        const unsigned n = G3D * SW0;
        for (unsigned i = t0; i < n; i += stride) {
            unsigned col = i % SW0;
            unsigned row = i / SW0;
            float v = (col < H1D) ? Wi0[row * H1D + col] : 0.0f;
            Wi0h[i] = __float2half_rn(v);
        }
    } else {
        const unsigned n = H2D * SW;
        for (unsigned i = t0; i < n; i += stride) {
            unsigned col = i & (SW - 1);
            unsigned row = i >> 11;
            float v = (col < HID) ? W2[row * HID + col] : 0.0f;
            W2h[i] = __float2half_rn(v);
        }
    }
}

// ---------------- init kernel (runs each replay, resets all state) ---------
__global__ void knet_init(const float* __restrict__ m1x0,
                          const float* __restrict__ F,
                          const float* __restrict__ Hm,
                          const float* __restrict__ h0) {
    int t = threadIdx.x;
    __shared__ float fm[M10];
    if (t == 0) { g_bar = 0u; g_epoch = 0u; }
    if (t < M10) {
        float s = 0.0f;
        for (int j = 0; j < M10; j++) s = fmaf(F[t * M10 + j], m1x0[j], s);
        fm[t] = s;
        g_post[t] = m1x0[t];
        g_prev_post[t] = 0.0f;
        g_prev_prior[t] = m1x0[t];
    }
    __syncthreads();
    if (t < M10) {
        float s = 0.0f;
        for (int j = 0; j < M10; j++) s = fmaf(Hm[t * M10 + j], fm[j], s);
        g_yprev[t] = s;
    }
    for (int i = t; i < HID; i += blockDim.x) {
        g_h1i[i] = h0[i];
        g_h2i[i] = h0[HID + i];
    }
}

// ---------------- epilogue of step te (one warp: CTA0/warp0) ---------------
__device__ __forceinline__ void epilogue(int te, int lane,
                                         const float* __restrict__ y,
                                         const float* __restrict__ F,
                                         const float* __restrict__ Hm,
                                         const float* __restrict__ W3,
                                         const float* __restrict__ b3,
                                         const float* __restrict__ b2,
                                         float* __restrict__ out,
                                         float* s_scr) {
    float* s_g  = s_scr;        // 400
    float* s_kg = s_scr + 400;  // 100
    float* s_pr = s_scr + 512;  // 10
    float* s_dy = s_scr + 528;  // 10

    for (int i = lane; i < H2D; i += 32) {
        float s = b2[i];
#pragma unroll
        for (int k = 0; k < NCH; k++) s += g_gp[i * NCH + k];
        s_g[i] = fmaxf(s, 0.0f);
    }
    __syncwarp();
    for (int r = lane; r < 100; r += 32) {
        const float* w = W3 + r * H2D;
        float s = b3[r];
        for (int j = 0; j < H2D; j += 4) {
            float4 a = *reinterpret_cast<const float4*>(w + j);
            s = fmaf(a.x, s_g[j],     s);
            s = fmaf(a.y, s_g[j + 1], s);
            s = fmaf(a.z, s_g[j + 2], s);
            s = fmaf(a.w, s_g[j + 3], s);
        }
        s_kg[r] = s;
    }
    __syncwarp();
    if (lane < M10) {
        float s = 0.0f;
        for (int j = 0; j < M10; j++) s = fmaf(F[lane * M10 + j], g_post[j], s);
        s_pr[lane] = s;
    }
    __syncwarp();
    if (lane < M10) {
        float m1y = 0.0f;
        for (int j = 0; j < M10; j++) m1y = fmaf(Hm[lane * M10 + j], s_pr[j], m1y);
        s_dy[lane] = y[lane * NTT + te] - m1y;
    }
    __syncwarp();
    if (lane < M10) {
        float np = s_pr[lane];
        for (int j = 0; j < M10; j++) np = fmaf(s_kg[lane * M10 + j], s_dy[j], np);
        g_prev_post[lane]  = g_post[lane];
        g_prev_prior[lane] = s_pr[lane];
        g_yprev[lane]      = y[lane * NTT + te];
        out[lane * NTT + te] = np;
        g_post[lane] = np;
    }
    __syncwarp();
}

// ---------------- main persistent kernel -----------------------------------
__global__ void __launch_bounds__(1024, 1)
knet_main(const float* __restrict__ y,
          const float* __restrict__ W1,  const float* __restrict__ b1,
          const float* __restrict__ bi0, const float* __restrict__ bh0,
          const float* __restrict__ bi1, const float* __restrict__ bh1,
          const float* __restrict__ b2,
          const float* __restrict__ W3,  const float* __restrict__ b3,
          const float* __restrict__ F,   const float* __restrict__ Hm,
          float* __restrict__ out) {
    __shared__ __align__(16) float s_h1[SW];    // padded, pad zeroed
    __shared__ __align__(16) float s_h2[SW];
    __shared__ __align__(16) float s_a[SW0];    // padded; doubles as epi scratch
    __shared__ float s_kin[DIN];

    const int tid  = threadIdx.x;
    const int lane = tid & 31;
    const int wid  = tid >> 5;
    const unsigned gw = blockIdx.x * 32u + (unsigned)wid;
    const unsigned NW = gridDim.x * 32u;

    for (int i = tid; i < SW; i += 1024) {
        s_h1[i] = (i < HID) ? g_h1i[i] : 0.0f;
        s_h2[i] = (i < HID) ? g_h2i[i] : 0.0f;
    }
    for (int i = tid; i < SW0; i += 1024) s_a[i] = 0.0f;
    __syncthreads();

    unsigned tgt = 0;

    for (int t = 0; t < NTT; ++t) {
        // ---- Phase 1a: prev-step epilogue (CTA0.warp0) overlapped with
        //      gh0 = Wh0@h1, gh1 = Wh1@h2 : 96000 chunk units, batch-2
        if (blockIdx.x == 0 && wid == 0 && t > 0) {
            epilogue(t - 1, lane, y, F, Hm, W3, b3, b2, out, s_a);
            if (lane == 0) {
                __threadfence();
                *(volatile unsigned*)&g_epoch = (unsigned)t;
            }
            __syncwarp();
        }
        for (unsigned u = gw; u < 96000u; u += 2u * NW) {
            unsigned u2 = u + NW;
            // unit A
            unsigned vA = (u < 48000u) ? u : (u - 48000u);
            const __half* wrA = ((u < 48000u) ? Wh0h : Wh1h) + (size_t)(vA >> 3) * SW;
            const float* vecA = (u < 48000u) ? s_h1 : s_h2;
            float sA = chunk_dot(wrA, vecA, (int)(vA & 7u), lane);
            float sB = 0.0f;
            unsigned vB = 0;
            bool hasB = (u2 < 96000u);
            if (hasB) {
                vB = (u2 < 48000u) ? u2 : (u2 - 48000u);
                const __half* wrB = ((u2 < 48000u) ? Wh0h : Wh1h) + (size_t)(vB >> 3) * SW;
                const float* vecB = (u2 < 48000u) ? s_h1 : s_h2;
                sB = chunk_dot(wrB, vecB, (int)(vB & 7u), lane);
            }
            sA = warp_sum(sA);
            sB = warp_sum(sB);
            if (lane == 0) {
                float* dA = (u < 48000u) ? g_gh0p : g_gh1p;
                dA[vA] = sA;
                if (hasB) {
                    float* dB = (u2 < 48000u) ? g_gh0p : g_gh1p;
                    dB[vB] = sB;
                }
            }
        }
        __syncthreads();

        // ---- Phase 1b: wait for state update, compute normalized features
        if (wid == 0) {
            while (*(volatile unsigned*)&g_epoch < (unsigned)t) { }
            __threadfence();
            float yt = 0.0f, p = 0.0f, pp = 0.0f, ppr = 0.0f, yp = 0.0f;
            if (lane < M10) {
                yt  = y[lane * NTT + t];
                p   = g_post[lane];
                pp  = g_prev_post[lane];
                ppr = g_prev_prior[lane];
                yp  = g_yprev[lane];
            }
            float d1 = yt - yp;
            float d3 = p - pp;
            float d4 = p - ppr;
            float n1 = fmaxf(sqrtf(warp_sum(d1 * d1)), 1e-12f);
            float n3 = fmaxf(sqrtf(warp_sum(d3 * d3)), 1e-12f);
            float n4 = fmaxf(sqrtf(warp_sum(d4 * d4)), 1e-12f);
            if (lane < M10) {
                s_kin[lane]      = d1 / n1;
                s_kin[10 + lane] = d3 / n3;
                s_kin[20 + lane] = d4 / n4;
            }
        }
        __syncthreads();

        // ---- Phase 1c: a = relu(W1 @ kin + b1)  (fp32, small)
        for (unsigned r = gw; r < (unsigned)H1D; r += NW) {
            float s = (lane < DIN) ? W1[r * DIN + lane] * s_kin[lane] : 0.0f;
            s = warp_sum(s);
            if (lane == 0) g_a[r] = fmaxf(s + b1[r], 0.0f);
        }
        tgt += gridDim.x; gsync(tgt);

        // ---- Phase 2: gi0 = Wi0 @ a  (42000 units of 7 chunks/row)
        for (int i = tid; i < H1D; i += 1024) s_a[i] = g_a[i];
        __syncthreads();
        for (unsigned u = gw; u < 42000u; u += 2u * NW) {
            unsigned u2 = u + NW;
            float sA = chunk_dot(Wi0h + (size_t)(u / 7u) * SW0, s_a, (int)(u % 7u), lane);
            float sB = 0.0f;
            bool hasB = (u2 < 42000u);
            if (hasB)
                sB = chunk_dot(Wi0h + (size_t)(u2 / 7u) * SW0, s_a, (int)(u2 % 7u), lane);
            sA = warp_sum(sA);
            sB = warp_sum(sB);
            if (lane == 0) {
                g_gi0p[u] = sA;
                if (hasB) g_gi0p[u2] = sB;
            }
        }
        tgt += gridDim.x; gsync(tgt);

        // ---- Phase 3: h1n combine (per-CTA, into s_h1) then gi1 = Wi1 @ h1n
        for (int j = tid; j < HID; j += 1024) {
            float ir = bi0[j], iz = bi0[j + HID], inn = bi0[j + 2 * HID];
            float hr = bh0[j], hz = bh0[j + HID], hn  = bh0[j + 2 * HID];
#pragma unroll
            for (int k = 0; k < NCH0; k++) {
                ir  += g_gi0p[(size_t)j * NCH0 + k];
                iz  += g_gi0p[(size_t)(j + HID) * NCH0 + k];
                inn += g_gi0p[(size_t)(j + 2 * HID) * NCH0 + k];
            }
#pragma unroll
            for (int k = 0; k < NCH; k++) {
                hr  += g_gh0p[(size_t)j * NCH + k];
                hz  += g_gh0p[(size_t)(j + HID) * NCH + k];
                hn  += g_gh0p[(size_t)(j + 2 * HID) * NCH + k];
            }
            float r  = sigmoidf_(ir + hr);
            float z  = sigmoidf_(iz + hz);
            float nn = tanhf_(inn + r * hn);
            float h  = s_h1[j];
            s_h1[j] = (1.0f - z) * nn + z * h;
        }
        __syncthreads();
        for (unsigned u = gw; u < 48000u; u += 2u * NW) {
            unsigned u2 = u + NW;
            float sA = chunk_dot(Wi1h + (size_t)(u >> 3) * SW, s_h1, (int)(u & 7u), lane);
            float sB = 0.0f;
            bool hasB = (u2 < 48000u);
            if (hasB)
                sB = chunk_dot(Wi1h + (size_t)(u2 >> 3) * SW, s_h1, (int)(u2 & 7u), lane);
            sA = warp_sum(sA);
            sB = warp_sum(sB);
            if (lane == 0) {
                g_gi1p[u] = sA;
                if (hasB) g_gi1p[u2] = sB;
            }
        }
        tgt += gridDim.x; gsync(tgt);

        // ---- Phase 4: h2n combine (into s_h2) then g partials = W2 @ h2n
        for (int j = tid; j < HID; j += 1024) {
            float ir = bi1[j], iz = bi1[j + HID], inn = bi1[j + 2 * HID];
            float hr = bh1[j], hz = bh1[j + HID], hn  = bh1[j + 2 * HID];
#pragma unroll
            for (int k = 0; k < NCH; k++) {
                ir  += g_gi1p[(size_t)j * NCH + k];
                iz  += g_gi1p[(size_t)(j + HID) * NCH + k];
                inn += g_gi1p[(size_t)(j + 2 * HID) * NCH + k];
                hr  += g_gh1p[(size_t)j * NCH + k];
                hz  += g_gh1p[(size_t)(j + HID) * NCH + k];
                hn  += g_gh1p[(size_t)(j + 2 * HID) * NCH + k];
            }
            float r  = sigmoidf_(ir + hr);
            float z  = sigmoidf_(iz + hz);
            float nn = tanhf_(inn + r * hn);
            float h  = s_h2[j];
            s_h2[j] = (1.0f - z) * nn + z * h;
        }
        __syncthreads();
        for (unsigned u = gw; u < 3200u; u += NW) {
            float s = chunk_dot(W2h + (size_t)(u >> 3) * SW, s_h2, (int)(u & 7u), lane);
            s = warp_sum(s);
            if (lane == 0) g_gp[u] = s;
        }
        tgt += gridDim.x; gsync(tgt);
    }

    if (blockIdx.x == 0 && wid == 0) {
        epilogue(NTT - 1, lane, y, F, Hm, W3, b3, b2, out, s_a);
    }
}

// ---------------- launcher --------------------------------------------------
extern "C" void kernel_launch(void* const* d_in, const int* in_sizes, int n_in,
                              void* d_out, int out_size) {
    (void)in_sizes; (void)n_in; (void)out_size;
    const float* y    = (const float*)d_in[0];
    const float* m1x0 = (const float*)d_in[1];
    const float* F    = (const float*)d_in[2];
    const float* Hm   = (const float*)d_in[3];
    const float* h0   = (const float*)d_in[4];
    const float* W1   = (const float*)d_in[5];
    const float* b1   = (const float*)d_in[6];
    const float* Wi0  = (const float*)d_in[7];
    const float* Wh0  = (const float*)d_in[8];
    const float* bi0  = (const float*)d_in[9];
    const float* bh0  = (const float*)d_in[10];
    const float* Wi1  = (const float*)d_in[11];
    const float* Wh1  = (const float*)d_in[12];
    const float* bi1  = (const float*)d_in[13];
    const float* bh1  = (const float*)d_in[14];
    const float* W2   = (const float*)d_in[15];
    const float* b2   = (const float*)d_in[16];
    const float* W3   = (const float*)d_in[17];
    const float* b3   = (const float*)d_in[18];
    float* out = (float*)d_out;

    int dev = 0;
    cudaGetDevice(&dev);
    int nsm = 148;
    cudaDeviceGetAttribute(&nsm, cudaDevAttrMultiProcessorCount, dev);

    knet_cvt<<<dim3(2 * nsm, 5), 256>>>(Wi0, Wh0, Wi1, Wh1, W2);
    knet_init<<<1, 128>>>(m1x0, F, Hm, h0);
    knet_main<<<nsm, 1024>>>(y, W1, b1, bi0, bh0, bi1, bh1,
                             b2, W3, b3, F, Hm, out);
}